// round 4
// baseline (speedup 1.0000x reference)
#include <cuda_runtime.h>
#include <math.h>
#include <stddef.h>

// Problem constants
#define Bz    32
#define T     1024
#define F     256
#define Hh    256
#define C3    768      // 3 live gate chunks (i, f, g)
#define NB    128      // persistent blocks
#define HB    2        // H columns per block (256/128)
#define NCOL  6        // HB * 3 chunks
#define NTH   256
#define OMEGA 32

// -------- device scratch (static allocation only; no cudaMalloc) --------
__device__ float        g_G[(size_t)T * C3 * Bz];   // [t][col][b] : a_cur cache (x@W' then += h@U')  ~96MB
__device__ float        g_xr[T * Bz];               // x_t @ W_r per (t,b)
__device__ float        g_hbuf[2][Bz * Hh];         // double-buffered h, [b][k]
__device__ unsigned int g_bar;                      // monotonic grid barrier counter

// ------------------------------------------------------------------
__global__ void init_kernel() {
    int tid = threadIdx.x;
    if (tid == 0) g_bar = 0u;
    float* hb = (float*)g_hbuf;
    for (int i = tid; i < 2 * Bz * Hh; i += NTH) hb[i] = 0.f;
}

// xr[t][b] = sum_f x[b,t,f] * W_r[f]
__global__ __launch_bounds__(256) void xr_kernel(const float* __restrict__ x,
                                                 const float* __restrict__ W_r) {
    int t = blockIdx.x;
    int tid = threadIdx.x;
    int b = tid >> 3, ks = tid & 7;
    const float4* xv = (const float4*)(x + ((size_t)b * T + t) * F);
    const float4* wr = (const float4*)W_r;
    float s = 0.f;
#pragma unroll
    for (int q = 0; q < 8; q++) {
        float4 a = xv[ks * 8 + q];
        float4 w = wr[ks * 8 + q];
        s += a.x * w.x + a.y * w.y + a.z * w.z + a.w * w.w;
    }
    s += __shfl_xor_sync(0xffffffffu, s, 1);
    s += __shfl_xor_sync(0xffffffffu, s, 2);
    s += __shfl_xor_sync(0xffffffffu, s, 4);
    if ((tid & 7) == 0) g_xr[t * Bz + b] = s;
}

// G[t][col][b] = sum_f x[b,t,f] * W[f,col], col < 768. Grid: (12 col-tiles, 1024 t).
__global__ __launch_bounds__(256) void gemm_kernel(const float* __restrict__ x,
                                                   const float* __restrict__ W) {
    __shared__ float xsh[Bz][33];
    __shared__ float wsh[32][64];
    int t = blockIdx.y;
    int colbase = blockIdx.x * 64;
    int tid = threadIdx.x;
    int b = tid & 31, cg = tid >> 5;
    float acc[8];
#pragma unroll
    for (int i = 0; i < 8; i++) acc[i] = 0.f;

    for (int kt = 0; kt < 8; kt++) {
        int k0 = kt * 32;
        __syncthreads();
        {
            int lb = tid >> 3, kq = tid & 7;
            float4 v = *(const float4*)(x + ((size_t)lb * T + t) * F + k0 + kq * 4);
            xsh[lb][kq * 4 + 0] = v.x; xsh[lb][kq * 4 + 1] = v.y;
            xsh[lb][kq * 4 + 2] = v.z; xsh[lb][kq * 4 + 3] = v.w;
            int kk = tid >> 3, c4 = (tid & 7) * 8;
            const float* wrow = W + (size_t)(k0 + kk) * 1024 + colbase + c4;
            float4 w0 = *(const float4*)(wrow);
            float4 w1 = *(const float4*)(wrow + 4);
            *(float4*)&wsh[kk][c4] = w0;
            *(float4*)&wsh[kk][c4 + 4] = w1;
        }
        __syncthreads();
#pragma unroll
        for (int kk = 0; kk < 32; kk++) {
            float xv = xsh[b][kk];
            float4 w0 = *(const float4*)&wsh[kk][cg * 8];
            float4 w1 = *(const float4*)&wsh[kk][cg * 8 + 4];
            acc[0] += xv * w0.x; acc[1] += xv * w0.y;
            acc[2] += xv * w0.z; acc[3] += xv * w0.w;
            acc[4] += xv * w1.x; acc[5] += xv * w1.y;
            acc[6] += xv * w1.z; acc[7] += xv * w1.w;
        }
    }
    size_t base = (size_t)t * (C3 * Bz) + (size_t)(colbase + cg * 8) * Bz + b;
#pragma unroll
    for (int i = 0; i < 8; i++) g_G[base + (size_t)i * Bz] = acc[i];
}

// ------------------------------------------------------------------
struct __align__(16) RecSmem {
    float hs[Bz][260];      // h, padded float4 rows (65 quads)
    float Ush[NCOL][260];   // 6 U' columns (static)
    float Ur[260];          // U_r (static)
    float Psh[Bz][68];      // P [32][64] padded (static)
    float pp[8][NCOL][Bz];  // per-warp partials of h@U'
    float gsh[NCOL][Bz];    // G[t] slice
    float ac[NCOL][Bz];     // a_cur slice
    float ar[NCOL][Bz];     // a_rec slice
    float gt[NCOL][Bz];     // gates slice
    float hrp[8][Bz];       // h@U_r partials
    float Prsh[Bz];
    float xrsh[Bz];
    float biassh[NCOL];
    int   s_idx;
};

__global__ __launch_bounds__(NTH, 1) void rec_kernel(
    const float* __restrict__ U, const float* __restrict__ P,
    const float* __restrict__ B_bias, const float* __restrict__ P_r,
    const float* __restrict__ U_r, const float* __restrict__ W_out,
    const float* __restrict__ b_out, float* __restrict__ out)
{
    extern __shared__ char smem_raw[];
    RecSmem& S = *reinterpret_cast<RecSmem*>(smem_raw);
    const int tid = threadIdx.x;
    const int w = tid >> 5, lane = tid & 31;
    const int j0 = blockIdx.x * HB;

    // ---- one-time preloads ----
    for (int i = tid; i < NCOL * Hh; i += NTH) {
        int cl = i >> 8, k = i & 255;
        int colg = (cl >> 1) * Hh + j0 + (cl & 1);
        S.Ush[cl][k] = U[(size_t)k * 1024 + colg];
    }
    for (int i = tid; i < Hh; i += NTH) S.Ur[i] = U_r[i];
    for (int i = tid; i < Bz * 64; i += NTH) S.Psh[i >> 6][i & 63] = P[i];
    if (tid < Bz) S.Prsh[tid] = P_r[tid];
    if (tid < NCOL) {
        int colg = (tid >> 1) * Hh + j0 + (tid & 1);
        S.biassh[tid] = B_bias[colg];
    }
    float c_reg = 0.f;   // c state for (jl = tid>>5, b = tid&31), tid < 64
    __syncthreads();

    for (int t = 0; t < T; t++) {
        // ---- grid barrier: wait until all blocks finished step t-1 ----
        if (t > 0) {
            if (tid == 0) {
                unsigned target = (unsigned)NB * (unsigned)t;
                unsigned v;
                do {
                    asm volatile("ld.global.acquire.gpu.u32 %0, [%1];"
                                 : "=r"(v) : "l"(&g_bar));
                } while (v < target);
            }
            __syncthreads();
        }

        // ---- load h (8KB), G[t] slice, xr[t] ----
        {
            const float4* hb = (const float4*)g_hbuf[t & 1];
#pragma unroll
            for (int r = 0; r < 8; r++) {
                int qi = tid + r * NTH;          // 0..2047
                int b = qi >> 6, q = qi & 63;
                ((float4*)&S.hs[b][0])[q] = hb[qi];
            }
            if (tid < 48) {
                int cl = tid >> 3, q = tid & 7;
                int colg = (cl >> 1) * Hh + j0 + (cl & 1);
                float4 v = *(const float4*)&g_G[(size_t)t * (C3 * Bz) + (size_t)colg * Bz + q * 4];
                *(float4*)&S.gsh[cl][q * 4] = v;
            } else if (tid < 56) {
                int q = tid - 48;
                float4 v = *(const float4*)&g_xr[t * Bz + q * 4];
                *(float4*)&S.xrsh[q * 4] = v;
            }
        }
        __syncthreads();

        // ---- h @ U_r partials ----
        {
            const float4* hrow = (const float4*)&S.hs[lane][0];
            const float4* ur = (const float4*)&S.Ur[0];
            float s = 0.f;
#pragma unroll
            for (int q = 0; q < 8; q++) {
                float4 hv = hrow[w * 8 + q], uv = ur[w * 8 + q];
                s += hv.x * uv.x + hv.y * uv.y + hv.z * uv.z + hv.w * uv.w;
            }
            S.hrp[w][lane] = s;
        }
        __syncthreads();

        // ---- warp0: recall gate + idx ----
        if (w == 0) {
            float hr = 0.f;
#pragma unroll
            for (int ks = 0; ks < 8; ks++) hr += S.hrp[ks][lane];
            float v = S.Prsh[lane] * (S.xrsh[lane] + hr);
#pragma unroll
            for (int o = 16; o; o >>= 1) v += __shfl_xor_sync(0xffffffffu, v, o);
            if (lane == 0) {
                float gate = 1.f / (1.f + expf(-v));
                int idx = (int)rintf((float)t * gate);   // round half-to-even, like jnp.round
                int hi = (t - 1) > 0 ? (t - 1) : 0;
                idx = idx < 0 ? 0 : (idx > hi ? hi : idx);
                S.s_idx = idx;
            }
        }

        // ---- main: h @ U' partials for 6 columns (all 8 warps, K-split) ----
        {
            float acc[NCOL];
#pragma unroll
            for (int cl = 0; cl < NCOL; cl++) acc[cl] = 0.f;
            const float4* hrow = (const float4*)&S.hs[lane][0];
#pragma unroll
            for (int q = 0; q < 8; q++) {
                float4 hv = hrow[w * 8 + q];
#pragma unroll
                for (int cl = 0; cl < NCOL; cl++) {
                    float4 uv = ((const float4*)&S.Ush[cl][0])[w * 8 + q];
                    acc[cl] += hv.x * uv.x + hv.y * uv.y + hv.z * uv.z + hv.w * uv.w;
                }
            }
#pragma unroll
            for (int cl = 0; cl < NCOL; cl++) S.pp[w][cl][lane] = acc[cl];
        }
        __syncthreads();

        // ---- reduce partials, finalize a_cur, store Am[t], stage a_rec ----
        if (tid < 192) {
            int cl = tid >> 5, b = tid & 31;
            int colg = (cl >> 1) * Hh + j0 + (cl & 1);
            bool self = (t < OMEGA);
            float arv = 0.f;
            if (!self) {
                int idx = S.s_idx;
                arv = g_G[(size_t)idx * (C3 * Bz) + (size_t)colg * Bz + b];
            }
            float s = S.gsh[cl][b];
#pragma unroll
            for (int ww = 0; ww < 8; ww++) s += S.pp[ww][cl][b];
            g_G[(size_t)t * (C3 * Bz) + (size_t)colg * Bz + b] = s;   // Am[t] = a_cur
            S.ac[cl][b] = s;
            S.ar[cl][b] = self ? s : arv;
        }
        __syncthreads();

        // ---- P-mix: gates = bias + P1 @ a_cur + P2 @ a_rec ----
        if (tid < 192) {
            int cl = tid >> 5, b = tid & 31;
            float g = S.biassh[cl];
            const float4* p1 = (const float4*)&S.Psh[b][0];
            const float4* p2 = (const float4*)&S.Psh[b][32];
            const float4* acp = (const float4*)&S.ac[cl][0];
            const float4* arp = (const float4*)&S.ar[cl][0];
#pragma unroll
            for (int q = 0; q < 8; q++) {
                float4 a = p1[q], c4 = acp[q];
                g += a.x * c4.x + a.y * c4.y + a.z * c4.z + a.w * c4.w;
                float4 d = p2[q], e = arp[q];
                g += d.x * e.x + d.y * e.y + d.z * e.z + d.w * e.w;
            }
            S.gt[cl][b] = g;
        }
        __syncthreads();

        // ---- activations + state update + publish h ----
        if (tid < 64) {
            int jl = tid >> 5, b = tid & 31;
            float iv = 1.f / (1.f + expf(-S.gt[jl][b]));
            float fv = 1.f / (1.f + expf(-S.gt[2 + jl][b]));
            float gv = tanhf(S.gt[4 + jl][b]);
            c_reg = fv * c_reg + iv * gv;
            float h = iv * tanhf(c_reg);       // o_t = i_t (faithful to source)
            g_hbuf[(t + 1) & 1][b * Hh + j0 + jl] = h;
        }
        __syncthreads();
        if (tid == 0) {
            __threadfence();
            atomicAdd(&g_bar, 1u);
        }
    }

    // ---- final: out = h_final @ W_out + b_out (block 0) ----
    if (tid == 0) {
        unsigned v;
        do {
            asm volatile("ld.global.acquire.gpu.u32 %0, [%1];" : "=r"(v) : "l"(&g_bar));
        } while (v < (unsigned)(NB * T));
    }
    __syncthreads();
    if (blockIdx.x == 0) {
        int b = tid >> 3, ks = tid & 7;
        const float4* hr4 = (const float4*)(g_hbuf[0] + b * Hh);   // T even -> final h in buf 0
        const float4* wo4 = (const float4*)W_out;
        float s = 0.f;
#pragma unroll
        for (int q = 0; q < 8; q++) {
            float4 hv = hr4[ks * 8 + q], wv = wo4[ks * 8 + q];
            s += hv.x * wv.x + hv.y * wv.y + hv.z * wv.z + hv.w * wv.w;
        }
        s += __shfl_xor_sync(0xffffffffu, s, 1);
        s += __shfl_xor_sync(0xffffffffu, s, 2);
        s += __shfl_xor_sync(0xffffffffu, s, 4);
        if (ks == 0) out[b] = s + b_out[0];
    }
}

// ------------------------------------------------------------------
extern "C" void kernel_launch(void* const* d_in, const int* in_sizes, int n_in,
                              void* d_out, int out_size) {
    const float* x      = (const float*)d_in[0];   // [32,1024,256]
    const float* W      = (const float*)d_in[1];   // [256,1024]
    const float* U      = (const float*)d_in[2];   // [256,1024]
    const float* P      = (const float*)d_in[3];   // [32,64]
    const float* B_bias = (const float*)d_in[4];   // [1024]
    const float* W_r    = (const float*)d_in[5];   // [256,1]
    const float* P_r    = (const float*)d_in[6];   // [1,32]
    const float* U_r    = (const float*)d_in[7];   // [256,1]
    const float* W_out  = (const float*)d_in[8];   // [256,1]
    const float* b_out  = (const float*)d_in[9];   // [1]
    float* out = (float*)d_out;                    // [32,1]

    (void)in_sizes; (void)n_in; (void)out_size;

    init_kernel<<<1, NTH>>>();
    xr_kernel<<<T, 256>>>(x, W_r);
    gemm_kernel<<<dim3(12, T), 256>>>(x, W);

    cudaFuncSetAttribute(rec_kernel, cudaFuncAttributeMaxDynamicSharedMemorySize,
                         (int)sizeof(RecSmem));
    rec_kernel<<<NB, NTH, sizeof(RecSmem)>>>(U, P, B_bias, P_r, U_r, W_out, b_out, out);
}